// round 1
// baseline (speedup 1.0000x reference)
#include <cuda_runtime.h>
#include <math.h>

// Problem constants (fixed shapes from the reference)
#define NN 50000
#define EE 800000
#define DD 64
#define KK 3
#define AGG_EPS 1e-6f
#define BN_EPS  1e-5f

// Scratch (device globals — no allocation allowed)
__device__ float g_Ax[NN * DD];
__device__ float g_Dx[NN * DD];
__device__ float g_Bx[KK * NN * DD];
__device__ float g_num[NN * KK * DD];
__device__ float g_den[NN * KK * DD];
__device__ float g_xnew[NN * DD];
__device__ float g_fsum[DD];
__device__ float g_fsq[DD];

// ---------------------------------------------------------------------------
// K0: zero the accumulators
// ---------------------------------------------------------------------------
__global__ void zero_kernel() {
    int idx = blockIdx.x * blockDim.x + threadIdx.x;
    int stride = gridDim.x * blockDim.x;
    const int tot = NN * KK * DD;
    for (int i = idx; i < tot; i += stride) {
        g_num[i] = 0.f;
        g_den[i] = 0.f;
    }
    if (idx < DD) {
        g_fsum[idx] = 0.f;
        g_fsq[idx]  = 0.f;
    }
}

// ---------------------------------------------------------------------------
// K1: five GEMMs (N x 64) @ (64 x 64), blockIdx.y selects which one.
//   m=0: Ax = xs[2] @ Wa + ba
//   m=1: Dx = xs[2] @ Wd + bd
//   m=2+k: Bx[k] = xs[2-k] @ Wb[k] + bb[k]   (delay(k+1)=k, nu=1, T=2)
// Block: 256 threads, tile of 32 rows. W cached in SMEM.
// ---------------------------------------------------------------------------
__global__ void gemm_kernel(const float* __restrict__ xs,
                            const float* __restrict__ Wa, const float* __restrict__ ba,
                            const float* __restrict__ Wd, const float* __restrict__ bd,
                            const float* __restrict__ Wb, const float* __restrict__ bb,
                            int N) {
    __shared__ float Ws[DD * DD];   // 16 KB
    __shared__ float Xs[32 * DD];   // 8 KB

    int m = blockIdx.y;
    const float* X; const float* W; const float* b; float* dst;
    if (m == 0)      { X = xs + 2 * (size_t)N * DD; W = Wa; b = ba; dst = g_Ax; }
    else if (m == 1) { X = xs + 2 * (size_t)N * DD; W = Wd; b = bd; dst = g_Dx; }
    else {
        int k = m - 2;  // 0..2
        X = xs + (size_t)(2 - k) * N * DD;
        W = Wb + (size_t)k * DD * DD;
        b = bb + k * DD;
        dst = g_Bx + (size_t)k * N * DD;
    }

    int t = threadIdx.x;
    for (int i = t; i < DD * DD; i += 256) Ws[i] = W[i];
    int row0 = blockIdx.x * 32;
    for (int i = t; i < 32 * DD; i += 256) {
        int r = row0 + i / DD;
        Xs[i] = (r < N) ? X[(size_t)r * DD + (i % DD)] : 0.f;
    }
    __syncthreads();

    int c = t & 63;         // output column
    int rbase = t >> 6;     // 0..3
    float bias = b[c];
    #pragma unroll
    for (int q = 0; q < 8; q++) {
        int rl = rbase + q * 4;       // local row 0..31 (increasing with q)
        int r = row0 + rl;
        if (r >= N) break;
        float acc = bias;
        #pragma unroll
        for (int kk = 0; kk < DD; kk++)
            acc += Xs[rl * DD + kk] * Ws[kk * DD + c];
        dst[(size_t)r * DD + c] = acc;
    }
}

// ---------------------------------------------------------------------------
// K2: edge kernel. One thread per (edge, float4 chunk). 16 chunks per edge.
// sigma = sigmoid(Dx[i] + Bx[ke, j]); scatter sigma*Bx and sigma into (i, ke).
// ---------------------------------------------------------------------------
__global__ void edge_kernel(const int* __restrict__ ei,   // [2, E]
                            const int* __restrict__ ea,   // [E]
                            int N, int E) {
    long tid = (long)blockIdx.x * blockDim.x + threadIdx.x;
    long tot = (long)E * 16;
    if (tid >= tot) return;
    int e  = (int)(tid >> 4);
    int c4 = (int)(tid & 15);

    int j  = ei[e];        // source
    int i  = ei[E + e];    // destination
    int ke = ea[e] - 1;    // 0..K-1

    const float4 dv = *(const float4*)&g_Dx[(size_t)i * DD + c4 * 4];
    const float4 bv = *(const float4*)&g_Bx[((size_t)ke * N + j) * DD + c4 * 4];

    float4 s;
    s.x = 1.f / (1.f + __expf(-(dv.x + bv.x)));
    s.y = 1.f / (1.f + __expf(-(dv.y + bv.y)));
    s.z = 1.f / (1.f + __expf(-(dv.z + bv.z)));
    s.w = 1.f / (1.f + __expf(-(dv.w + bv.w)));

    size_t base = ((size_t)i * KK + ke) * DD + c4 * 4;
    atomicAdd(&g_num[base + 0], s.x * bv.x);
    atomicAdd(&g_num[base + 1], s.y * bv.y);
    atomicAdd(&g_num[base + 2], s.z * bv.z);
    atomicAdd(&g_num[base + 3], s.w * bv.w);
    atomicAdd(&g_den[base + 0], s.x);
    atomicAdd(&g_den[base + 1], s.y);
    atomicAdd(&g_den[base + 2], s.z);
    atomicAdd(&g_den[base + 3], s.w);
}

// ---------------------------------------------------------------------------
// K3: combine: x_new = Ax + (1/K) * sum_k num/(den+eps); accumulate per-feature
// sums and sums-of-squares for BatchNorm stats.
// Block: 256 threads, 32 rows per block (same layout as gemm_kernel).
// ---------------------------------------------------------------------------
__global__ void combine_kernel(int N) {
    __shared__ float ssum[DD];
    __shared__ float ssq[DD];
    int t = threadIdx.x;
    if (t < DD) { ssum[t] = 0.f; ssq[t] = 0.f; }
    __syncthreads();

    int c = t & 63;
    int rbase = t >> 6;
    int row0 = blockIdx.x * 32;
    float lsum = 0.f, lsq = 0.f;
    #pragma unroll
    for (int q = 0; q < 8; q++) {
        int n = row0 + rbase + q * 4;
        if (n >= N) break;
        float acc = 0.f;
        #pragma unroll
        for (int k = 0; k < KK; k++) {
            size_t idx = ((size_t)n * KK + k) * DD + c;
            acc += g_num[idx] / (g_den[idx] + AGG_EPS);
        }
        float v = g_Ax[(size_t)n * DD + c] + acc * (1.f / KK);
        g_xnew[(size_t)n * DD + c] = v;
        lsum += v;
        lsq  += v * v;
    }
    atomicAdd(&ssum[c], lsum);
    atomicAdd(&ssq[c],  lsq);
    __syncthreads();
    if (t < DD) {
        atomicAdd(&g_fsum[t], ssum[t]);
        atomicAdd(&g_fsq[t],  ssq[t]);
    }
}

// ---------------------------------------------------------------------------
// K4: BatchNorm (training-mode batch stats, biased var) + ReLU
// ---------------------------------------------------------------------------
__global__ void bn_kernel(const float* __restrict__ gamma,
                          const float* __restrict__ beta,
                          float* __restrict__ out, int N) {
    int idx = blockIdx.x * blockDim.x + threadIdx.x;
    if (idx >= N * DD) return;
    int d = idx & 63;
    float invN = 1.f / (float)N;
    float mean = g_fsum[d] * invN;
    float var  = g_fsq[d] * invN - mean * mean;
    float y = gamma[d] * (g_xnew[idx] - mean) * rsqrtf(var + BN_EPS) + beta[d];
    out[idx] = fmaxf(y, 0.f);
}

// ---------------------------------------------------------------------------
extern "C" void kernel_launch(void* const* d_in, const int* in_sizes, int n_in,
                              void* d_out, int out_size) {
    const float* xs    = (const float*)d_in[0];   // [T+1, N, D]
    const int*   ei    = (const int*)d_in[1];     // [2, E]
    const int*   ea    = (const int*)d_in[2];     // [E]
    const float* Wa    = (const float*)d_in[3];
    const float* ba    = (const float*)d_in[4];
    const float* Wd    = (const float*)d_in[5];
    const float* bd    = (const float*)d_in[6];
    const float* Wb    = (const float*)d_in[7];   // [K, D, D]
    const float* bb    = (const float*)d_in[8];   // [K, D]
    const float* gamma = (const float*)d_in[9];
    const float* beta  = (const float*)d_in[10];
    float* out = (float*)d_out;

    int N = in_sizes[0] / ((2 + 1) * DD);   // T+1 = 3 states
    int E = in_sizes[2];

    zero_kernel<<<4096, 256>>>();

    dim3 gGemm((N + 31) / 32, 5);
    gemm_kernel<<<gGemm, 256>>>(xs, Wa, ba, Wd, bd, Wb, bb, N);

    long edgeThreads = (long)E * 16;
    int edgeBlocks = (int)((edgeThreads + 255) / 256);
    edge_kernel<<<edgeBlocks, 256>>>(ei, ea, N, E);

    combine_kernel<<<(N + 31) / 32, 256>>>(N);

    bn_kernel<<<(N * DD + 255) / 256, 256>>>(gamma, beta, out, N);
}

// round 2
// speedup vs baseline: 1.5352x; 1.5352x over previous
#include <cuda_runtime.h>
#include <math.h>

#define NN 50000
#define EE 800000
#define DD 64
#define KK 3
#define NKMAX (NN * KK)
#define AGG_EPS 1e-6f
#define BN_EPS  1e-5f
#define SCAN_BLK 1024
#define MAXBLKS 256   // ceil(150000/1024)=147

// Scratch (device globals — no allocation allowed)
__device__ float g_Ax[NN * DD];
__device__ float g_Dx[NN * DD];
__device__ float g_Bx[KK * NN * DD];
__device__ float g_xnew[NN * DD];
__device__ float g_fsum[DD];
__device__ float g_fsq[DD];

__device__ int g_count[NKMAX];
__device__ int g_partial[NKMAX];
__device__ int g_blocksum[MAXBLKS];
__device__ int g_blockoff[MAXBLKS];
__device__ int g_segstart[NKMAX + 1];
__device__ int g_cursor[NKMAX];
__device__ int g_sorted[EE];

// ---------------------------------------------------------------------------
// K0: zero the histogram + BN accumulators
// ---------------------------------------------------------------------------
__global__ void zero_kernel(int NK) {
    int idx = blockIdx.x * blockDim.x + threadIdx.x;
    int stride = gridDim.x * blockDim.x;
    for (int i = idx; i < NK; i += stride) g_count[i] = 0;
    if (idx < DD) { g_fsum[idx] = 0.f; g_fsq[idx] = 0.f; }
}

// ---------------------------------------------------------------------------
// K1: histogram of edges per segment (seg = i*K + ke)
// ---------------------------------------------------------------------------
__global__ void hist_kernel(const int* __restrict__ ei, const int* __restrict__ ea, int E) {
    int e = blockIdx.x * blockDim.x + threadIdx.x;
    if (e >= E) return;
    int i  = ei[E + e];
    int ke = ea[e] - 1;
    atomicAdd(&g_count[i * KK + ke], 1);
}

// ---------------------------------------------------------------------------
// K2a: per-block exclusive scan (Hillis-Steele on 1024 elems)
// ---------------------------------------------------------------------------
__global__ void scan1_kernel(int NK) {
    __shared__ int sh[SCAN_BLK];
    int t = threadIdx.x;
    int idx = blockIdx.x * SCAN_BLK + t;
    int v = (idx < NK) ? g_count[idx] : 0;
    sh[t] = v;
    __syncthreads();
    #pragma unroll
    for (int off = 1; off < SCAN_BLK; off <<= 1) {
        int x = (t >= off) ? sh[t - off] : 0;
        __syncthreads();
        sh[t] += x;
        __syncthreads();
    }
    if (idx < NK) g_partial[idx] = sh[t] - v;
    if (t == SCAN_BLK - 1) g_blocksum[blockIdx.x] = sh[t];
}

// K2b: scan block sums (single block)
__global__ void scan2_kernel(int nblocks) {
    __shared__ int sh[MAXBLKS];
    int t = threadIdx.x;
    int v = (t < nblocks) ? g_blocksum[t] : 0;
    sh[t] = v;
    __syncthreads();
    #pragma unroll
    for (int off = 1; off < MAXBLKS; off <<= 1) {
        int x = (t >= off) ? sh[t - off] : 0;
        __syncthreads();
        sh[t] += x;
        __syncthreads();
    }
    if (t < nblocks) g_blockoff[t] = sh[t] - v;
}

// K2c: combine partial scans -> segstart + cursor
__global__ void scan3_kernel(int NK, int E) {
    int idx = blockIdx.x * blockDim.x + threadIdx.x;
    if (idx < NK) {
        int v = g_partial[idx] + g_blockoff[idx >> 10];
        g_segstart[idx] = v;
        g_cursor[idx] = v;
    }
    if (idx == 0) g_segstart[NK] = E;
}

// ---------------------------------------------------------------------------
// K3: scatter source node ids into sorted order
// ---------------------------------------------------------------------------
__global__ void scatter_kernel(const int* __restrict__ ei, const int* __restrict__ ea, int E) {
    int e = blockIdx.x * blockDim.x + threadIdx.x;
    if (e >= E) return;
    int j  = ei[e];
    int i  = ei[E + e];
    int ke = ea[e] - 1;
    int pos = atomicAdd(&g_cursor[i * KK + ke], 1);
    g_sorted[pos] = j;
}

// ---------------------------------------------------------------------------
// K4: five GEMMs (N x 64) @ (64 x 64), blockIdx.y selects which one.
// ---------------------------------------------------------------------------
__global__ void gemm_kernel(const float* __restrict__ xs,
                            const float* __restrict__ Wa, const float* __restrict__ ba,
                            const float* __restrict__ Wd, const float* __restrict__ bd,
                            const float* __restrict__ Wb, const float* __restrict__ bb,
                            int N) {
    __shared__ float Ws[DD * DD];
    __shared__ float Xs[32 * DD];

    int m = blockIdx.y;
    const float* X; const float* W; const float* b; float* dst;
    if (m == 0)      { X = xs + 2 * (size_t)N * DD; W = Wa; b = ba; dst = g_Ax; }
    else if (m == 1) { X = xs + 2 * (size_t)N * DD; W = Wd; b = bd; dst = g_Dx; }
    else {
        int k = m - 2;
        X = xs + (size_t)(2 - k) * N * DD;
        W = Wb + (size_t)k * DD * DD;
        b = bb + k * DD;
        dst = g_Bx + (size_t)k * N * DD;
    }

    int t = threadIdx.x;
    for (int i = t; i < DD * DD; i += 256) Ws[i] = W[i];
    int row0 = blockIdx.x * 32;
    for (int i = t; i < 32 * DD; i += 256) {
        int r = row0 + i / DD;
        Xs[i] = (r < N) ? X[(size_t)r * DD + (i % DD)] : 0.f;
    }
    __syncthreads();

    int c = t & 63;
    int rbase = t >> 6;
    float bias = b[c];
    #pragma unroll
    for (int q = 0; q < 8; q++) {
        int rl = rbase + q * 4;
        int r = row0 + rl;
        if (r >= N) break;
        float acc = bias;
        #pragma unroll
        for (int kk = 0; kk < DD; kk++)
            acc += Xs[rl * DD + kk] * Ws[kk * DD + c];
        dst[(size_t)r * DD + c] = acc;
    }
}

// ---------------------------------------------------------------------------
// K5: segmented aggregation, fused with combine + BN-stat accumulation.
// One warp per node; each lane owns dims {2*lane, 2*lane+1}.
// ---------------------------------------------------------------------------
__global__ void agg_kernel(int N) {
    __shared__ float ssum[DD];
    __shared__ float ssq[DD];
    int t = threadIdx.x;
    if (t < DD) { ssum[t] = 0.f; ssq[t] = 0.f; }
    __syncthreads();

    int warp = (blockIdx.x * blockDim.x + t) >> 5;
    int lane = t & 31;

    if (warp < N) {
        int n = warp;
        float2 d = *(const float2*)&g_Dx[(size_t)n * DD + lane * 2];
        float eta0 = 0.f, eta1 = 0.f;
        #pragma unroll
        for (int k = 0; k < KK; k++) {
            int s = g_segstart[n * KK + k];
            int e = g_segstart[n * KK + k + 1];
            const float* Bk = g_Bx + (size_t)k * N * DD;
            float num0 = 0.f, num1 = 0.f, den0 = 0.f, den1 = 0.f;
            for (int p = s; p < e; p++) {
                int j = __ldg(&g_sorted[p]);
                float2 b = *(const float2*)&Bk[(size_t)j * DD + lane * 2];
                float s0 = 1.f / (1.f + __expf(-(d.x + b.x)));
                float s1 = 1.f / (1.f + __expf(-(d.y + b.y)));
                num0 += s0 * b.x; den0 += s0;
                num1 += s1 * b.y; den1 += s1;
            }
            eta0 += num0 / (den0 + AGG_EPS);
            eta1 += num1 / (den1 + AGG_EPS);
        }
        float2 a = *(const float2*)&g_Ax[(size_t)n * DD + lane * 2];
        float v0 = a.x + eta0 * (1.f / KK);
        float v1 = a.y + eta1 * (1.f / KK);
        float2 vo; vo.x = v0; vo.y = v1;
        *(float2*)&g_xnew[(size_t)n * DD + lane * 2] = vo;
        atomicAdd(&ssum[lane * 2 + 0], v0);
        atomicAdd(&ssum[lane * 2 + 1], v1);
        atomicAdd(&ssq[lane * 2 + 0], v0 * v0);
        atomicAdd(&ssq[lane * 2 + 1], v1 * v1);
    }
    __syncthreads();
    if (t < DD) {
        atomicAdd(&g_fsum[t], ssum[t]);
        atomicAdd(&g_fsq[t],  ssq[t]);
    }
}

// ---------------------------------------------------------------------------
// K6: BatchNorm (batch stats, biased var) + ReLU
// ---------------------------------------------------------------------------
__global__ void bn_kernel(const float* __restrict__ gamma,
                          const float* __restrict__ beta,
                          float* __restrict__ out, int N) {
    int idx = blockIdx.x * blockDim.x + threadIdx.x;
    if (idx >= N * DD) return;
    int d = idx & 63;
    float invN = 1.f / (float)N;
    float mean = g_fsum[d] * invN;
    float var  = g_fsq[d] * invN - mean * mean;
    float y = gamma[d] * (g_xnew[idx] - mean) * rsqrtf(var + BN_EPS) + beta[d];
    out[idx] = fmaxf(y, 0.f);
}

// ---------------------------------------------------------------------------
extern "C" void kernel_launch(void* const* d_in, const int* in_sizes, int n_in,
                              void* d_out, int out_size) {
    const float* xs    = (const float*)d_in[0];
    const int*   ei    = (const int*)d_in[1];
    const int*   ea    = (const int*)d_in[2];
    const float* Wa    = (const float*)d_in[3];
    const float* ba    = (const float*)d_in[4];
    const float* Wd    = (const float*)d_in[5];
    const float* bd    = (const float*)d_in[6];
    const float* Wb    = (const float*)d_in[7];
    const float* bb    = (const float*)d_in[8];
    const float* gamma = (const float*)d_in[9];
    const float* beta  = (const float*)d_in[10];
    float* out = (float*)d_out;

    int N = in_sizes[0] / (3 * DD);
    int E = in_sizes[2];
    int NK = N * KK;
    int nScanBlks = (NK + SCAN_BLK - 1) / SCAN_BLK;

    zero_kernel<<<256, 256>>>(NK);
    hist_kernel<<<(E + 255) / 256, 256>>>(ei, ea, E);
    scan1_kernel<<<nScanBlks, SCAN_BLK>>>(NK);
    scan2_kernel<<<1, MAXBLKS>>>(nScanBlks);
    scan3_kernel<<<(NK + 255) / 256, 256>>>(NK, E);
    scatter_kernel<<<(E + 255) / 256, 256>>>(ei, ea, E);

    dim3 gGemm((N + 31) / 32, 5);
    gemm_kernel<<<gGemm, 256>>>(xs, Wa, ba, Wd, bd, Wb, bb, N);

    int aggBlocks = (N * 32 + 255) / 256;
    agg_kernel<<<aggBlocks, 256>>>(N);

    bn_kernel<<<(N * DD + 255) / 256, 256>>>(gamma, beta, out, N);
}

// round 3
// speedup vs baseline: 2.3088x; 1.5039x over previous
#include <cuda_runtime.h>
#include <math.h>

#define NN 50000
#define EE 800000
#define DD 64
#define KK 3
#define NKMAX (NN * KK)
#define AGG_EPS 1e-6f
#define BN_EPS  1e-5f
#define SCAN_BLK 1024
#define MAXBLKS 256
#define XPAD 72   // padded stride for transposed X tile in SMEM

// Scratch (device globals — no allocation allowed)
__device__ float g_Dx[NN * DD];
__device__ float g_Bx[KK * NN * DD];
__device__ float g_xnew[NN * DD];     // gemm writes Ax here; agg atomically adds eta/K
__device__ float g_fsum[DD];
__device__ float g_fsq[DD];

__device__ int g_count[NKMAX];
__device__ int g_partial[NKMAX];
__device__ int g_blocksum[MAXBLKS];
__device__ int g_blockoff[MAXBLKS];
__device__ int g_segstart[NKMAX + 1];
__device__ int g_cursor[NKMAX];
__device__ int g_sorted[EE];

// ---------------------------------------------------------------------------
// K0: zero histogram + BN accumulators
// ---------------------------------------------------------------------------
__global__ void zero_kernel(int NK) {
    int idx = blockIdx.x * blockDim.x + threadIdx.x;
    int stride = gridDim.x * blockDim.x;
    for (int i = idx; i < NK; i += stride) g_count[i] = 0;
    if (idx < DD) { g_fsum[idx] = 0.f; g_fsq[idx] = 0.f; }
}

// ---------------------------------------------------------------------------
// K1: histogram of edges per segment (seg = i*K + ke)
// ---------------------------------------------------------------------------
__global__ void hist_kernel(const int* __restrict__ ei, const int* __restrict__ ea, int E) {
    int e = blockIdx.x * blockDim.x + threadIdx.x;
    if (e >= E) return;
    int i  = ei[E + e];
    int ke = ea[e] - 1;
    atomicAdd(&g_count[i * KK + ke], 1);
}

// ---------------------------------------------------------------------------
// K2a/b/c: 3-level exclusive scan
// ---------------------------------------------------------------------------
__global__ void scan1_kernel(int NK) {
    __shared__ int sh[SCAN_BLK];
    int t = threadIdx.x;
    int idx = blockIdx.x * SCAN_BLK + t;
    int v = (idx < NK) ? g_count[idx] : 0;
    sh[t] = v;
    __syncthreads();
    #pragma unroll
    for (int off = 1; off < SCAN_BLK; off <<= 1) {
        int x = (t >= off) ? sh[t - off] : 0;
        __syncthreads();
        sh[t] += x;
        __syncthreads();
    }
    if (idx < NK) g_partial[idx] = sh[t] - v;
    if (t == SCAN_BLK - 1) g_blocksum[blockIdx.x] = sh[t];
}

__global__ void scan2_kernel(int nblocks) {
    __shared__ int sh[MAXBLKS];
    int t = threadIdx.x;
    int v = (t < nblocks) ? g_blocksum[t] : 0;
    sh[t] = v;
    __syncthreads();
    #pragma unroll
    for (int off = 1; off < MAXBLKS; off <<= 1) {
        int x = (t >= off) ? sh[t - off] : 0;
        __syncthreads();
        sh[t] += x;
        __syncthreads();
    }
    if (t < nblocks) g_blockoff[t] = sh[t] - v;
}

__global__ void scan3_kernel(int NK, int E) {
    int idx = blockIdx.x * blockDim.x + threadIdx.x;
    if (idx < NK) {
        int v = g_partial[idx] + g_blockoff[idx >> 10];
        g_segstart[idx] = v;
        g_cursor[idx] = v;
    }
    if (idx == 0) g_segstart[NK] = E;
}

// ---------------------------------------------------------------------------
// K3: scatter source node ids into sorted order
// ---------------------------------------------------------------------------
__global__ void scatter_kernel(const int* __restrict__ ei, const int* __restrict__ ea, int E) {
    int e = blockIdx.x * blockDim.x + threadIdx.x;
    if (e >= E) return;
    int j  = ei[e];
    int i  = ei[E + e];
    int ke = ea[e] - 1;
    int pos = atomicAdd(&g_cursor[i * KK + ke], 1);
    g_sorted[pos] = j;
}

// ---------------------------------------------------------------------------
// K4: five GEMMs, register-tiled. 64x64 tile per 256-thread block, 4x4 per
// thread. m=0 (Ax) writes into g_xnew (serves as the combine base).
// ---------------------------------------------------------------------------
__global__ void gemm_kernel(const float* __restrict__ xs,
                            const float* __restrict__ Wa, const float* __restrict__ ba,
                            const float* __restrict__ Wd, const float* __restrict__ bd,
                            const float* __restrict__ Wb, const float* __restrict__ bb,
                            int N) {
    __shared__ float Ws[DD * DD];        // W row-major: Ws[kk*64 + c]
    __shared__ float XsT[DD * XPAD];     // transposed: XsT[kk*XPAD + r]

    int m = blockIdx.y;
    const float* X; const float* W; const float* b; float* dst;
    if (m == 0)      { X = xs + 2 * (size_t)N * DD; W = Wa; b = ba; dst = g_xnew; }
    else if (m == 1) { X = xs + 2 * (size_t)N * DD; W = Wd; b = bd; dst = g_Dx; }
    else {
        int k = m - 2;
        X = xs + (size_t)(2 - k) * N * DD;
        W = Wb + (size_t)k * DD * DD;
        b = bb + k * DD;
        dst = g_Bx + (size_t)k * N * DD;
    }

    int t = threadIdx.x;
    int row0 = blockIdx.x * 64;

    for (int i = t; i < DD * DD; i += 256) Ws[i] = W[i];
    for (int i = t; i < 64 * DD; i += 256) {
        int r  = i >> 6;          // local row 0..63
        int kk = i & 63;
        int gr = row0 + r;
        XsT[kk * XPAD + r] = (gr < N) ? X[(size_t)gr * DD + kk] : 0.f;
    }
    __syncthreads();

    int tx = t & 15;        // col group
    int ty = t >> 4;        // row group
    int c0 = tx * 4;
    int r0 = ty * 4;

    float acc[4][4];
    #pragma unroll
    for (int i = 0; i < 4; i++)
        #pragma unroll
        for (int jj = 0; jj < 4; jj++) acc[i][jj] = 0.f;

    #pragma unroll 4
    for (int kk = 0; kk < DD; kk++) {
        float4 av = *(const float4*)&XsT[kk * XPAD + r0];
        float4 bv = *(const float4*)&Ws[kk * DD + c0];
        acc[0][0] += av.x * bv.x; acc[0][1] += av.x * bv.y; acc[0][2] += av.x * bv.z; acc[0][3] += av.x * bv.w;
        acc[1][0] += av.y * bv.x; acc[1][1] += av.y * bv.y; acc[1][2] += av.y * bv.z; acc[1][3] += av.y * bv.w;
        acc[2][0] += av.z * bv.x; acc[2][1] += av.z * bv.y; acc[2][2] += av.z * bv.z; acc[2][3] += av.z * bv.w;
        acc[3][0] += av.w * bv.x; acc[3][1] += av.w * bv.y; acc[3][2] += av.w * bv.z; acc[3][3] += av.w * bv.w;
    }

    float4 bias = *(const float4*)&b[c0];
    #pragma unroll
    for (int i = 0; i < 4; i++) {
        int gr = row0 + r0 + i;
        if (gr < N) {
            float4 o;
            o.x = acc[i][0] + bias.x;
            o.y = acc[i][1] + bias.y;
            o.z = acc[i][2] + bias.z;
            o.w = acc[i][3] + bias.w;
            *(float4*)&dst[(size_t)gr * DD + c0] = o;
        }
    }
}

// ---------------------------------------------------------------------------
// K5: segmented aggregation. One warp per (node, k) segment; lane owns 2 dims.
// Edge indices are loaded 32-at-a-time and shfl-broadcast. Partial eta/K is
// atomically added into g_xnew (pre-initialized with Ax by gemm).
// ---------------------------------------------------------------------------
__global__ void agg_kernel(int N) {
    int gw   = (blockIdx.x * blockDim.x + threadIdx.x) >> 5;
    int lane = threadIdx.x & 31;
    if (gw >= N * KK) return;
    int n = gw / KK;
    int k = gw - n * KK;

    int s = g_segstart[gw];
    int e = g_segstart[gw + 1];

    float2 d = *(const float2*)&g_Dx[(size_t)n * DD + lane * 2];
    const float* Bk = g_Bx + (size_t)k * N * DD;

    float num0 = 0.f, num1 = 0.f, den0 = 0.f, den1 = 0.f;
    for (int base = s; base < e; base += 32) {
        int idx = base + lane;
        int jv = (idx < e) ? __ldg(&g_sorted[idx]) : 0;
        int cnt = min(32, e - base);
        for (int mm = 0; mm < cnt; mm++) {
            int j = __shfl_sync(0xffffffff, jv, mm);
            float2 b = *(const float2*)&Bk[(size_t)j * DD + lane * 2];
            float s0 = 1.f / (1.f + __expf(-(d.x + b.x)));
            float s1 = 1.f / (1.f + __expf(-(d.y + b.y)));
            num0 += s0 * b.x; den0 += s0;
            num1 += s1 * b.y; den1 += s1;
        }
    }

    float eta0 = num0 / (den0 + AGG_EPS) * (1.f / KK);
    float eta1 = num1 / (den1 + AGG_EPS) * (1.f / KK);
    atomicAdd(&g_xnew[(size_t)n * DD + lane * 2 + 0], eta0);
    atomicAdd(&g_xnew[(size_t)n * DD + lane * 2 + 1], eta1);
}

// ---------------------------------------------------------------------------
// K6: BN statistics (per-feature sum / sum-of-squares)
// ---------------------------------------------------------------------------
__global__ void bnstat_kernel(int N) {
    __shared__ float ssum[DD];
    __shared__ float ssq[DD];
    int t = threadIdx.x;
    if (t < DD) { ssum[t] = 0.f; ssq[t] = 0.f; }
    __syncthreads();

    int d = t & 63;
    float lsum = 0.f, lsq = 0.f;
    int stride = gridDim.x * blockDim.x;
    for (int idx = blockIdx.x * blockDim.x + t; idx < N * DD; idx += stride) {
        float v = g_xnew[idx];
        lsum += v;
        lsq  += v * v;
    }
    atomicAdd(&ssum[d], lsum);
    atomicAdd(&ssq[d],  lsq);
    __syncthreads();
    if (t < DD) {
        atomicAdd(&g_fsum[t], ssum[t]);
        atomicAdd(&g_fsq[t],  ssq[t]);
    }
}

// ---------------------------------------------------------------------------
// K7: BatchNorm (batch stats, biased var) + ReLU
// ---------------------------------------------------------------------------
__global__ void bn_kernel(const float* __restrict__ gamma,
                          const float* __restrict__ beta,
                          float* __restrict__ out, int N) {
    int idx = blockIdx.x * blockDim.x + threadIdx.x;
    if (idx >= N * DD) return;
    int d = idx & 63;
    float invN = 1.f / (float)N;
    float mean = g_fsum[d] * invN;
    float var  = g_fsq[d] * invN - mean * mean;
    float y = gamma[d] * (g_xnew[idx] - mean) * rsqrtf(var + BN_EPS) + beta[d];
    out[idx] = fmaxf(y, 0.f);
}

// ---------------------------------------------------------------------------
extern "C" void kernel_launch(void* const* d_in, const int* in_sizes, int n_in,
                              void* d_out, int out_size) {
    const float* xs    = (const float*)d_in[0];
    const int*   ei    = (const int*)d_in[1];
    const int*   ea    = (const int*)d_in[2];
    const float* Wa    = (const float*)d_in[3];
    const float* ba    = (const float*)d_in[4];
    const float* Wd    = (const float*)d_in[5];
    const float* bd    = (const float*)d_in[6];
    const float* Wb    = (const float*)d_in[7];
    const float* bb    = (const float*)d_in[8];
    const float* gamma = (const float*)d_in[9];
    const float* beta  = (const float*)d_in[10];
    float* out = (float*)d_out;

    int N = in_sizes[0] / (3 * DD);
    int E = in_sizes[2];
    int NK = N * KK;
    int nScanBlks = (NK + SCAN_BLK - 1) / SCAN_BLK;

    zero_kernel<<<256, 256>>>(NK);
    hist_kernel<<<(E + 255) / 256, 256>>>(ei, ea, E);
    scan1_kernel<<<nScanBlks, SCAN_BLK>>>(NK);
    scan2_kernel<<<1, MAXBLKS>>>(nScanBlks);
    scan3_kernel<<<(NK + 255) / 256, 256>>>(NK, E);
    scatter_kernel<<<(E + 255) / 256, 256>>>(ei, ea, E);

    dim3 gGemm((N + 63) / 64, 5);
    gemm_kernel<<<gGemm, 256>>>(xs, Wa, ba, Wd, bd, Wb, bb, N);

    int aggBlocks = (NK * 32 + 255) / 256;
    agg_kernel<<<aggBlocks, 256>>>(N);

    bnstat_kernel<<<592, 256>>>(N);
    bn_kernel<<<(N * DD + 255) / 256, 256>>>(gamma, beta, out, N);
}

// round 4
// speedup vs baseline: 2.6506x; 1.1480x over previous
#include <cuda_runtime.h>
#include <math.h>

#define NN 50000
#define EE 800000
#define DD 64
#define KK 3
#define NKMAX (NN * KK)
#define AGG_EPS 1e-6f
#define BN_EPS  1e-5f
#define SCAN_BLK 1024
#define MAXBLKS 256
#define XPAD 72

// Scratch (device globals — no allocation allowed)
__device__ float g_Dx[NN * DD];
__device__ float g_Bx[KK * NN * DD];
__device__ float g_xnew[NN * DD];     // gemm writes Ax here; agg atomically adds eta/K
__device__ float g_fsum[DD];
__device__ float g_fsq[DD];

__device__ int g_count[NKMAX];
__device__ int g_partial[NKMAX];
__device__ int g_blocksum[MAXBLKS];
__device__ int g_segstart[NKMAX + 1];
__device__ int g_cursor[NKMAX];
__device__ int g_sorted[EE];

// ---------------------------------------------------------------------------
// K0: zero histogram + BN accumulators
// ---------------------------------------------------------------------------
__global__ void zero_kernel(int NK) {
    int idx = blockIdx.x * blockDim.x + threadIdx.x;
    int stride = gridDim.x * blockDim.x;
    for (int i = idx; i < NK; i += stride) g_count[i] = 0;
    if (idx < DD) { g_fsum[idx] = 0.f; g_fsq[idx] = 0.f; }
}

// ---------------------------------------------------------------------------
// K1: histogram of edges per segment (seg = i*K + ke)
// ---------------------------------------------------------------------------
__global__ void hist_kernel(const int* __restrict__ ei, const int* __restrict__ ea, int E) {
    int e = blockIdx.x * blockDim.x + threadIdx.x;
    if (e >= E) return;
    int i  = ei[E + e];
    int ke = ea[e] - 1;
    atomicAdd(&g_count[i * KK + ke], 1);
}

// ---------------------------------------------------------------------------
// K2a: per-block exclusive scan (shfl-based)
// ---------------------------------------------------------------------------
__global__ void scan1_kernel(int NK) {
    __shared__ int warpsum[32];
    int t = threadIdx.x;
    int lane = t & 31;
    int w = t >> 5;
    int idx = blockIdx.x * SCAN_BLK + t;
    int v = (idx < NK) ? g_count[idx] : 0;

    // inclusive warp scan
    int x = v;
    #pragma unroll
    for (int off = 1; off < 32; off <<= 1) {
        int y = __shfl_up_sync(0xffffffff, x, off);
        if (lane >= off) x += y;
    }
    if (lane == 31) warpsum[w] = x;
    __syncthreads();
    if (w == 0) {
        int s = (lane < SCAN_BLK / 32) ? warpsum[lane] : 0;
        #pragma unroll
        for (int off = 1; off < 32; off <<= 1) {
            int y = __shfl_up_sync(0xffffffff, s, off);
            if (lane >= off) s += y;
        }
        if (lane < SCAN_BLK / 32) warpsum[lane] = s;
    }
    __syncthreads();
    int wpre = (w > 0) ? warpsum[w - 1] : 0;
    int incl = x + wpre;
    if (idx < NK) g_partial[idx] = incl - v;   // exclusive
    if (t == SCAN_BLK - 1) g_blocksum[blockIdx.x] = incl;
}

// K2b: fused block-offset scan + apply. Each block computes the prefix of the
// (<=147) block sums in SMEM itself, then writes segstart/cursor.
__global__ void scan23_kernel(int NK, int E, int nblocks) {
    __shared__ int boff[MAXBLKS];
    int t = threadIdx.x;
    // one warp scans the block sums (nblocks <= 147 < 160 = 5*32)
    if (t < 32) {
        int acc = 0;
        for (int base = 0; base < nblocks; base += 32) {
            int idx = base + t;
            int v = (idx < nblocks) ? g_blocksum[idx] : 0;
            int x = v;
            #pragma unroll
            for (int off = 1; off < 32; off <<= 1) {
                int y = __shfl_up_sync(0xffffffff, x, off);
                if (t >= off) x += y;
            }
            if (idx < nblocks) boff[idx] = acc + x - v;  // exclusive
            acc += __shfl_sync(0xffffffff, x, 31);
        }
    }
    __syncthreads();
    int idx = blockIdx.x * blockDim.x + t;
    if (idx < NK) {
        int v = g_partial[idx] + boff[idx >> 10];
        g_segstart[idx] = v;
        g_cursor[idx] = v;
    }
    if (idx == 0) g_segstart[NK] = E;
}

// ---------------------------------------------------------------------------
// K3: scatter source node ids into sorted order
// ---------------------------------------------------------------------------
__global__ void scatter_kernel(const int* __restrict__ ei, const int* __restrict__ ea, int E) {
    int e = blockIdx.x * blockDim.x + threadIdx.x;
    if (e >= E) return;
    int j  = ei[e];
    int i  = ei[E + e];
    int ke = ea[e] - 1;
    int pos = atomicAdd(&g_cursor[i * KK + ke], 1);
    g_sorted[pos] = j;
}

// ---------------------------------------------------------------------------
// K4: five GEMMs, register-tiled 64x64 per 256-thread block, 4x4 per thread.
// m=0 (Ax) writes into g_xnew.
// ---------------------------------------------------------------------------
__global__ void gemm_kernel(const float* __restrict__ xs,
                            const float* __restrict__ Wa, const float* __restrict__ ba,
                            const float* __restrict__ Wd, const float* __restrict__ bd,
                            const float* __restrict__ Wb, const float* __restrict__ bb,
                            int N) {
    __shared__ float Ws[DD * DD];
    __shared__ float XsT[DD * XPAD];

    int m = blockIdx.y;
    const float* X; const float* W; const float* b; float* dst;
    if (m == 0)      { X = xs + 2 * (size_t)N * DD; W = Wa; b = ba; dst = g_xnew; }
    else if (m == 1) { X = xs + 2 * (size_t)N * DD; W = Wd; b = bd; dst = g_Dx; }
    else {
        int k = m - 2;
        X = xs + (size_t)(2 - k) * N * DD;
        W = Wb + (size_t)k * DD * DD;
        b = bb + k * DD;
        dst = g_Bx + (size_t)k * N * DD;
    }

    int t = threadIdx.x;
    int row0 = blockIdx.x * 64;

    for (int i = t; i < DD * DD; i += 256) Ws[i] = W[i];
    for (int i = t; i < 64 * DD; i += 256) {
        int r  = i >> 6;
        int kk = i & 63;
        int gr = row0 + r;
        XsT[kk * XPAD + r] = (gr < N) ? X[(size_t)gr * DD + kk] : 0.f;
    }
    __syncthreads();

    int tx = t & 15;
    int ty = t >> 4;
    int c0 = tx * 4;
    int r0 = ty * 4;

    float acc[4][4];
    #pragma unroll
    for (int i = 0; i < 4; i++)
        #pragma unroll
        for (int jj = 0; jj < 4; jj++) acc[i][jj] = 0.f;

    #pragma unroll 4
    for (int kk = 0; kk < DD; kk++) {
        float4 av = *(const float4*)&XsT[kk * XPAD + r0];
        float4 bv = *(const float4*)&Ws[kk * DD + c0];
        acc[0][0] += av.x * bv.x; acc[0][1] += av.x * bv.y; acc[0][2] += av.x * bv.z; acc[0][3] += av.x * bv.w;
        acc[1][0] += av.y * bv.x; acc[1][1] += av.y * bv.y; acc[1][2] += av.y * bv.z; acc[1][3] += av.y * bv.w;
        acc[2][0] += av.z * bv.x; acc[2][1] += av.z * bv.y; acc[2][2] += av.z * bv.z; acc[2][3] += av.z * bv.w;
        acc[3][0] += av.w * bv.x; acc[3][1] += av.w * bv.y; acc[3][2] += av.w * bv.z; acc[3][3] += av.w * bv.w;
    }

    float4 bias = *(const float4*)&b[c0];
    #pragma unroll
    for (int i = 0; i < 4; i++) {
        int gr = row0 + r0 + i;
        if (gr < N) {
            float4 o;
            o.x = acc[i][0] + bias.x;
            o.y = acc[i][1] + bias.y;
            o.z = acc[i][2] + bias.z;
            o.w = acc[i][3] + bias.w;
            *(float4*)&dst[(size_t)gr * DD + c0] = o;
        }
    }
}

// ---------------------------------------------------------------------------
// K5: segmented aggregation. One warp per (node, k) segment; lane owns 2 dims.
// ---------------------------------------------------------------------------
__global__ void agg_kernel(int N) {
    int gw   = (blockIdx.x * blockDim.x + threadIdx.x) >> 5;
    int lane = threadIdx.x & 31;
    if (gw >= N * KK) return;

    int s = g_segstart[gw];
    int e = g_segstart[gw + 1];
    if (s == e) return;

    int n = gw / KK;
    int k = gw - n * KK;

    float2 d = *(const float2*)&g_Dx[(size_t)n * DD + lane * 2];
    const float* Bk = g_Bx + (size_t)k * N * DD;

    float num0 = 0.f, num1 = 0.f, den0 = 0.f, den1 = 0.f;
    for (int base = s; base < e; base += 32) {
        int idx = base + lane;
        int jv = (idx < e) ? __ldg(&g_sorted[idx]) : 0;
        int cnt = min(32, e - base);
        for (int mm = 0; mm < cnt; mm++) {
            int j = __shfl_sync(0xffffffff, jv, mm);
            float2 b = *(const float2*)&Bk[(size_t)j * DD + lane * 2];
            float s0 = __fdividef(1.f, 1.f + __expf(-(d.x + b.x)));
            float s1 = __fdividef(1.f, 1.f + __expf(-(d.y + b.y)));
            num0 += s0 * b.x; den0 += s0;
            num1 += s1 * b.y; den1 += s1;
        }
    }

    float eta0 = __fdividef(num0, den0 + AGG_EPS) * (1.f / KK);
    float eta1 = __fdividef(num1, den1 + AGG_EPS) * (1.f / KK);
    atomicAdd(&g_xnew[(size_t)n * DD + lane * 2 + 0], eta0);
    atomicAdd(&g_xnew[(size_t)n * DD + lane * 2 + 1], eta1);
}

// ---------------------------------------------------------------------------
// K6: BN statistics
// ---------------------------------------------------------------------------
__global__ void bnstat_kernel(int N) {
    __shared__ float ssum[DD];
    __shared__ float ssq[DD];
    int t = threadIdx.x;
    if (t < DD) { ssum[t] = 0.f; ssq[t] = 0.f; }
    __syncthreads();

    int d = t & 63;
    float lsum = 0.f, lsq = 0.f;
    int stride = gridDim.x * blockDim.x;
    for (int idx = blockIdx.x * blockDim.x + t; idx < N * DD; idx += stride) {
        float v = g_xnew[idx];
        lsum += v;
        lsq  += v * v;
    }
    atomicAdd(&ssum[d], lsum);
    atomicAdd(&ssq[d],  lsq);
    __syncthreads();
    if (t < DD) {
        atomicAdd(&g_fsum[t], ssum[t]);
        atomicAdd(&g_fsq[t],  ssq[t]);
    }
}

// ---------------------------------------------------------------------------
// K7: BatchNorm + ReLU
// ---------------------------------------------------------------------------
__global__ void bn_kernel(const float* __restrict__ gamma,
                          const float* __restrict__ beta,
                          float* __restrict__ out, int N) {
    int idx = blockIdx.x * blockDim.x + threadIdx.x;
    if (idx >= N * DD) return;
    int d = idx & 63;
    float invN = 1.f / (float)N;
    float mean = g_fsum[d] * invN;
    float var  = g_fsq[d] * invN - mean * mean;
    float y = gamma[d] * (g_xnew[idx] - mean) * rsqrtf(var + BN_EPS) + beta[d];
    out[idx] = fmaxf(y, 0.f);
}

// ---------------------------------------------------------------------------
extern "C" void kernel_launch(void* const* d_in, const int* in_sizes, int n_in,
                              void* d_out, int out_size) {
    const float* xs    = (const float*)d_in[0];
    const int*   ei    = (const int*)d_in[1];
    const int*   ea    = (const int*)d_in[2];
    const float* Wa    = (const float*)d_in[3];
    const float* ba    = (const float*)d_in[4];
    const float* Wd    = (const float*)d_in[5];
    const float* bd    = (const float*)d_in[6];
    const float* Wb    = (const float*)d_in[7];
    const float* bb    = (const float*)d_in[8];
    const float* gamma = (const float*)d_in[9];
    const float* beta  = (const float*)d_in[10];
    float* out = (float*)d_out;

    int N = in_sizes[0] / (3 * DD);
    int E = in_sizes[2];
    int NK = N * KK;
    int nScanBlks = (NK + SCAN_BLK - 1) / SCAN_BLK;

    // One-time host-side resources (no device memory involved)
    static cudaStream_t side = nullptr;
    static cudaEvent_t evFork = nullptr, evJoin = nullptr;
    if (!side) {
        cudaStreamCreateWithFlags(&side, cudaStreamNonBlocking);
        cudaEventCreateWithFlags(&evFork, cudaEventDisableTiming);
        cudaEventCreateWithFlags(&evJoin, cudaEventDisableTiming);
    }

    // Fork: sort pipeline on side stream, GEMMs on main (default) stream.
    cudaEventRecord(evFork, 0);
    cudaStreamWaitEvent(side, evFork, 0);

    zero_kernel<<<256, 256, 0, side>>>(NK);
    hist_kernel<<<(E + 255) / 256, 256, 0, side>>>(ei, ea, E);
    scan1_kernel<<<nScanBlks, SCAN_BLK, 0, side>>>(NK);
    scan23_kernel<<<(NK + 255) / 256, 256, 0, side>>>(NK, E, nScanBlks);
    scatter_kernel<<<(E + 255) / 256, 256, 0, side>>>(ei, ea, E);

    dim3 gGemm((N + 63) / 64, 5);
    gemm_kernel<<<gGemm, 256>>>(xs, Wa, ba, Wd, bd, Wb, bb, N);

    // Join
    cudaEventRecord(evJoin, side);
    cudaStreamWaitEvent(0, evJoin, 0);

    int aggBlocks = (NK * 32 + 255) / 256;
    agg_kernel<<<aggBlocks, 256>>>(N);

    bnstat_kernel<<<592, 256>>>(N);
    bn_kernel<<<(N * DD + 255) / 256, 256>>>(gamma, beta, out, N);
}

// round 5
// speedup vs baseline: 2.6718x; 1.0080x over previous
#include <cuda_runtime.h>
#include <math.h>

#define NN 50000
#define EE 800000
#define DD 64
#define KK 3
#define NKMAX (NN * KK)
#define AGG_EPS 1e-6f
#define BN_EPS  1e-5f
#define SCAN_BLK 1024
#define MAXBLKS 256
#define XPAD 72

// Scratch (device globals — no allocation allowed)
__device__ float g_Dx[NN * DD];
__device__ float g_Bx[KK * NN * DD];
__device__ float g_xnew[NN * DD];     // gemm writes Ax; agg overwrites with x_new
__device__ float g_fsum[DD];
__device__ float g_fsq[DD];

__device__ int g_count[NKMAX];
__device__ int g_partial[NKMAX];
__device__ int g_blocksum[MAXBLKS];
__device__ int g_segstart[NKMAX + 1];
__device__ int g_cursor[NKMAX];
__device__ int g_sorted[EE];

__device__ __forceinline__ float tanh_fast(float x) {
    float y;
    asm("tanh.approx.f32 %0, %1;" : "=f"(y) : "f"(x));
    return y;
}
__device__ __forceinline__ float sigmoid_fast(float x) {
    return fmaf(tanh_fast(0.5f * x), 0.5f, 0.5f);
}

// ---------------------------------------------------------------------------
// K0: zero histogram + BN accumulators
// ---------------------------------------------------------------------------
__global__ void zero_kernel(int NK) {
    int idx = blockIdx.x * blockDim.x + threadIdx.x;
    int stride = gridDim.x * blockDim.x;
    for (int i = idx; i < NK; i += stride) g_count[i] = 0;
    if (idx < DD) { g_fsum[idx] = 0.f; g_fsq[idx] = 0.f; }
}

// ---------------------------------------------------------------------------
// K1: histogram of edges per segment (seg = i*K + ke)
// ---------------------------------------------------------------------------
__global__ void hist_kernel(const int* __restrict__ ei, const int* __restrict__ ea, int E) {
    int e = blockIdx.x * blockDim.x + threadIdx.x;
    if (e >= E) return;
    int i  = ei[E + e];
    int ke = ea[e] - 1;
    atomicAdd(&g_count[i * KK + ke], 1);
}

// ---------------------------------------------------------------------------
// K2a: per-block exclusive scan (shfl-based)
// ---------------------------------------------------------------------------
__global__ void scan1_kernel(int NK) {
    __shared__ int warpsum[32];
    int t = threadIdx.x;
    int lane = t & 31;
    int w = t >> 5;
    int idx = blockIdx.x * SCAN_BLK + t;
    int v = (idx < NK) ? g_count[idx] : 0;

    int x = v;
    #pragma unroll
    for (int off = 1; off < 32; off <<= 1) {
        int y = __shfl_up_sync(0xffffffff, x, off);
        if (lane >= off) x += y;
    }
    if (lane == 31) warpsum[w] = x;
    __syncthreads();
    if (w == 0) {
        int s = (lane < SCAN_BLK / 32) ? warpsum[lane] : 0;
        #pragma unroll
        for (int off = 1; off < 32; off <<= 1) {
            int y = __shfl_up_sync(0xffffffff, s, off);
            if (lane >= off) s += y;
        }
        if (lane < SCAN_BLK / 32) warpsum[lane] = s;
    }
    __syncthreads();
    int wpre = (w > 0) ? warpsum[w - 1] : 0;
    int incl = x + wpre;
    if (idx < NK) g_partial[idx] = incl - v;
    if (t == SCAN_BLK - 1) g_blocksum[blockIdx.x] = incl;
}

// K2b: fused block-offset scan + apply
__global__ void scan23_kernel(int NK, int E, int nblocks) {
    __shared__ int boff[MAXBLKS];
    int t = threadIdx.x;
    if (t < 32) {
        int acc = 0;
        for (int base = 0; base < nblocks; base += 32) {
            int idx = base + t;
            int v = (idx < nblocks) ? g_blocksum[idx] : 0;
            int x = v;
            #pragma unroll
            for (int off = 1; off < 32; off <<= 1) {
                int y = __shfl_up_sync(0xffffffff, x, off);
                if (t >= off) x += y;
            }
            if (idx < nblocks) boff[idx] = acc + x - v;
            acc += __shfl_sync(0xffffffff, x, 31);
        }
    }
    __syncthreads();
    int idx = blockIdx.x * blockDim.x + t;
    if (idx < NK) {
        int v = g_partial[idx] + boff[idx >> 10];
        g_segstart[idx] = v;
        g_cursor[idx] = v;
    }
    if (idx == 0) g_segstart[NK] = E;
}

// ---------------------------------------------------------------------------
// K3: scatter source node ids into sorted order
// ---------------------------------------------------------------------------
__global__ void scatter_kernel(const int* __restrict__ ei, const int* __restrict__ ea, int E) {
    int e = blockIdx.x * blockDim.x + threadIdx.x;
    if (e >= E) return;
    int j  = ei[e];
    int i  = ei[E + e];
    int ke = ea[e] - 1;
    int pos = atomicAdd(&g_cursor[i * KK + ke], 1);
    g_sorted[pos] = j;
}

// ---------------------------------------------------------------------------
// K4: five GEMMs, register-tiled 64x64 per 256-thread block, 4x4 per thread.
// m=0 (Ax) writes into g_xnew.
// ---------------------------------------------------------------------------
__global__ void gemm_kernel(const float* __restrict__ xs,
                            const float* __restrict__ Wa, const float* __restrict__ ba,
                            const float* __restrict__ Wd, const float* __restrict__ bd,
                            const float* __restrict__ Wb, const float* __restrict__ bb,
                            int N) {
    __shared__ float Ws[DD * DD];
    __shared__ float XsT[DD * XPAD];

    int m = blockIdx.y;
    const float* X; const float* W; const float* b; float* dst;
    if (m == 0)      { X = xs + 2 * (size_t)N * DD; W = Wa; b = ba; dst = g_xnew; }
    else if (m == 1) { X = xs + 2 * (size_t)N * DD; W = Wd; b = bd; dst = g_Dx; }
    else {
        int k = m - 2;
        X = xs + (size_t)(2 - k) * N * DD;
        W = Wb + (size_t)k * DD * DD;
        b = bb + k * DD;
        dst = g_Bx + (size_t)k * N * DD;
    }

    int t = threadIdx.x;
    int row0 = blockIdx.x * 64;

    for (int i = t; i < DD * DD; i += 256) Ws[i] = W[i];
    for (int i = t; i < 64 * DD; i += 256) {
        int r  = i >> 6;
        int kk = i & 63;
        int gr = row0 + r;
        XsT[kk * XPAD + r] = (gr < N) ? X[(size_t)gr * DD + kk] : 0.f;
    }
    __syncthreads();

    int tx = t & 15;
    int ty = t >> 4;
    int c0 = tx * 4;
    int r0 = ty * 4;

    float acc[4][4];
    #pragma unroll
    for (int i = 0; i < 4; i++)
        #pragma unroll
        for (int jj = 0; jj < 4; jj++) acc[i][jj] = 0.f;

    #pragma unroll 4
    for (int kk = 0; kk < DD; kk++) {
        float4 av = *(const float4*)&XsT[kk * XPAD + r0];
        float4 bv = *(const float4*)&Ws[kk * DD + c0];
        acc[0][0] += av.x * bv.x; acc[0][1] += av.x * bv.y; acc[0][2] += av.x * bv.z; acc[0][3] += av.x * bv.w;
        acc[1][0] += av.y * bv.x; acc[1][1] += av.y * bv.y; acc[1][2] += av.y * bv.z; acc[1][3] += av.y * bv.w;
        acc[2][0] += av.z * bv.x; acc[2][1] += av.z * bv.y; acc[2][2] += av.z * bv.z; acc[2][3] += av.z * bv.w;
        acc[3][0] += av.w * bv.x; acc[3][1] += av.w * bv.y; acc[3][2] += av.w * bv.z; acc[3][3] += av.w * bv.w;
    }

    float4 bias = *(const float4*)&b[c0];
    #pragma unroll
    for (int i = 0; i < 4; i++) {
        int gr = row0 + r0 + i;
        if (gr < N) {
            float4 o;
            o.x = acc[i][0] + bias.x;
            o.y = acc[i][1] + bias.y;
            o.z = acc[i][2] + bias.z;
            o.w = acc[i][3] + bias.w;
            *(float4*)&dst[(size_t)gr * DD + c0] = o;
        }
    }
}

// ---------------------------------------------------------------------------
// K5: fused aggregation + combine + BN stats.
// One warp per node. Lane halves process 2 edges at a time; each lane owns
// 4 dims (float4). Edge indices batched 32 at a time + shfl-broadcast.
// ---------------------------------------------------------------------------
__global__ void agg_kernel(int N) {
    __shared__ float ssum[DD];
    __shared__ float ssq[DD];
    int t = threadIdx.x;
    if (t < DD) { ssum[t] = 0.f; ssq[t] = 0.f; }
    __syncthreads();

    int warp = (blockIdx.x * blockDim.x + t) >> 5;
    int lane = t & 31;
    int half = lane >> 4;       // 0: edge 2m, 1: edge 2m+1
    int hl   = lane & 15;       // dim group: dims hl*4..hl*4+3

    if (warp < N) {
        int n = warp;
        float4 d = *(const float4*)&g_Dx[(size_t)n * DD + hl * 4];
        float4 eta = make_float4(0.f, 0.f, 0.f, 0.f);

        #pragma unroll
        for (int k = 0; k < KK; k++) {
            int s = g_segstart[n * KK + k];
            int e = g_segstart[n * KK + k + 1];
            const float* Bk = g_Bx + (size_t)k * N * DD;

            float4 num = make_float4(0.f, 0.f, 0.f, 0.f);
            float4 den = make_float4(0.f, 0.f, 0.f, 0.f);

            for (int base = s; base < e; base += 32) {
                int li = base + lane;
                int jv = (li < e) ? __ldg(&g_sorted[li]) : 0;
                int cnt = min(32, e - base);          // edges in this batch
                int npairs = (cnt + 1) >> 1;
                for (int mm = 0; mm < npairs; mm++) {
                    int j = __shfl_sync(0xffffffff, jv, 2 * mm + half);
                    int eidx = base + 2 * mm + half;
                    if (eidx < e) {
                        float4 b = *(const float4*)&Bk[(size_t)j * DD + hl * 4];
                        float s0 = sigmoid_fast(d.x + b.x);
                        float s1 = sigmoid_fast(d.y + b.y);
                        float s2 = sigmoid_fast(d.z + b.z);
                        float s3 = sigmoid_fast(d.w + b.w);
                        num.x += s0 * b.x; den.x += s0;
                        num.y += s1 * b.y; den.y += s1;
                        num.z += s2 * b.z; den.z += s2;
                        num.w += s3 * b.w; den.w += s3;
                    }
                }
            }
            // combine the two halves (same dims, disjoint edges)
            num.x += __shfl_xor_sync(0xffffffff, num.x, 16);
            num.y += __shfl_xor_sync(0xffffffff, num.y, 16);
            num.z += __shfl_xor_sync(0xffffffff, num.z, 16);
            num.w += __shfl_xor_sync(0xffffffff, num.w, 16);
            den.x += __shfl_xor_sync(0xffffffff, den.x, 16);
            den.y += __shfl_xor_sync(0xffffffff, den.y, 16);
            den.z += __shfl_xor_sync(0xffffffff, den.z, 16);
            den.w += __shfl_xor_sync(0xffffffff, den.w, 16);

            eta.x += __fdividef(num.x, den.x + AGG_EPS);
            eta.y += __fdividef(num.y, den.y + AGG_EPS);
            eta.z += __fdividef(num.z, den.z + AGG_EPS);
            eta.w += __fdividef(num.w, den.w + AGG_EPS);
        }

        float4 a = *(const float4*)&g_xnew[(size_t)n * DD + hl * 4];  // Ax
        float4 v;
        v.x = a.x + eta.x * (1.f / KK);
        v.y = a.y + eta.y * (1.f / KK);
        v.z = a.z + eta.z * (1.f / KK);
        v.w = a.w + eta.w * (1.f / KK);

        if (half == 0) {
            *(float4*)&g_xnew[(size_t)n * DD + hl * 4] = v;
            atomicAdd(&ssum[hl * 4 + 0], v.x);
            atomicAdd(&ssum[hl * 4 + 1], v.y);
            atomicAdd(&ssum[hl * 4 + 2], v.z);
            atomicAdd(&ssum[hl * 4 + 3], v.w);
        } else {
            atomicAdd(&ssq[hl * 4 + 0], v.x * v.x);
            atomicAdd(&ssq[hl * 4 + 1], v.y * v.y);
            atomicAdd(&ssq[hl * 4 + 2], v.z * v.z);
            atomicAdd(&ssq[hl * 4 + 3], v.w * v.w);
        }
    }
    __syncthreads();
    if (t < DD) {
        atomicAdd(&g_fsum[t], ssum[t]);
        atomicAdd(&g_fsq[t],  ssq[t]);
    }
}

// ---------------------------------------------------------------------------
// K6: BatchNorm + ReLU (vectorized)
// ---------------------------------------------------------------------------
__global__ void bn_kernel(const float* __restrict__ gamma,
                          const float* __restrict__ beta,
                          float* __restrict__ out, int N) {
    int idx = blockIdx.x * blockDim.x + threadIdx.x;   // float4 index
    if (idx >= N * (DD / 4)) return;
    int d4 = (idx & 15) * 4;
    float invN = 1.f / (float)N;
    float4 x = *(const float4*)&g_xnew[(size_t)idx * 4];
    float4 o;
    #pragma unroll
    for (int i = 0; i < 4; i++) {
        int d = d4 + i;
        float mean = g_fsum[d] * invN;
        float var  = g_fsq[d] * invN - mean * mean;
        float xi = (i == 0) ? x.x : (i == 1) ? x.y : (i == 2) ? x.z : x.w;
        float y = gamma[d] * (xi - mean) * rsqrtf(var + BN_EPS) + beta[d];
        y = fmaxf(y, 0.f);
        if (i == 0) o.x = y; else if (i == 1) o.y = y; else if (i == 2) o.z = y; else o.w = y;
    }
    *(float4*)&out[(size_t)idx * 4] = o;
}

// ---------------------------------------------------------------------------
extern "C" void kernel_launch(void* const* d_in, const int* in_sizes, int n_in,
                              void* d_out, int out_size) {
    const float* xs    = (const float*)d_in[0];
    const int*   ei    = (const int*)d_in[1];
    const int*   ea    = (const int*)d_in[2];
    const float* Wa    = (const float*)d_in[3];
    const float* ba    = (const float*)d_in[4];
    const float* Wd    = (const float*)d_in[5];
    const float* bd    = (const float*)d_in[6];
    const float* Wb    = (const float*)d_in[7];
    const float* bb    = (const float*)d_in[8];
    const float* gamma = (const float*)d_in[9];
    const float* beta  = (const float*)d_in[10];
    float* out = (float*)d_out;

    int N = in_sizes[0] / (3 * DD);
    int E = in_sizes[2];
    int NK = N * KK;
    int nScanBlks = (NK + SCAN_BLK - 1) / SCAN_BLK;

    static cudaStream_t side = nullptr;
    static cudaEvent_t evFork = nullptr, evJoin = nullptr;
    if (!side) {
        cudaStreamCreateWithFlags(&side, cudaStreamNonBlocking);
        cudaEventCreateWithFlags(&evFork, cudaEventDisableTiming);
        cudaEventCreateWithFlags(&evJoin, cudaEventDisableTiming);
    }

    cudaEventRecord(evFork, 0);
    cudaStreamWaitEvent(side, evFork, 0);

    zero_kernel<<<256, 256, 0, side>>>(NK);
    hist_kernel<<<(E + 255) / 256, 256, 0, side>>>(ei, ea, E);
    scan1_kernel<<<nScanBlks, SCAN_BLK, 0, side>>>(NK);
    scan23_kernel<<<(NK + 255) / 256, 256, 0, side>>>(NK, E, nScanBlks);
    scatter_kernel<<<(E + 255) / 256, 256, 0, side>>>(ei, ea, E);

    dim3 gGemm((N + 63) / 64, 5);
    gemm_kernel<<<gGemm, 256>>>(xs, Wa, ba, Wd, bd, Wb, bb, N);

    cudaEventRecord(evJoin, side);
    cudaStreamWaitEvent(0, evJoin, 0);

    agg_kernel<<<(N * 32 + 255) / 256, 256>>>(N);

    bn_kernel<<<(N * (DD / 4) + 255) / 256, 256>>>(gamma, beta, out, N);
}